// round 9
// baseline (speedup 1.0000x reference)
#include <cuda_runtime.h>
#include <cuda_bf16.h>

#define N_NODES   100000
#define N_EDGES   1600000
#define NUM_RELS  200
#define IN_FEAT   20
#define OUT_FEAT  20

// Fixed-capacity relation bins: mean 8000 edges/rel, sd ~89. CAP = +7.9 sigma.
#define CAP        8704
#define TOTAL_SLOTS (NUM_RELS * CAP)

// Padded W layout in SMEM: per relation 4 blocks x 28 floats (25 used, 3 pad)
// => every base block 16B-aligned for LDS.128 broadcasts.
#define W_BLK_STRIDE 28
#define W_REL_STRIDE (4 * W_BLK_STRIDE)            // 112 floats
#define SM_W_OFF   0
#define SM_GW_OFF  (NUM_RELS * W_REL_STRIDE)       // 22400
#define SM_FLOATS  (SM_GW_OFF + NUM_RELS * 20)     // 26400
#define SM_BYTES   (SM_FLOATS * 4)                 // 105600 -> 2 CTAs/SM

// ---------------------------------------------------------------------------
// Static scratch (no cudaMalloc allowed)
// ---------------------------------------------------------------------------
__device__ int  g_cursor[NUM_RELS];
__device__ int2 g_edges_s[TOTAL_SLOTS];   // (src, dst) in rel-strided bins

__device__ __forceinline__ void red_add_v4(float* addr, float a, float b, float c, float d) {
    asm volatile("red.global.add.v4.f32 [%0], {%1, %2, %3, %4};"
                 :: "l"(addr), "f"(a), "f"(b), "f"(c), "f"(d)
                 : "memory");
}

// ---------------------------------------------------------------------------
// Scatter: ONE SMEM-atomic pass. The pass-1 atomicAdd return IS the local
// rank; keep (r,s,d,rank) in registers across the reservation barrier.
// Block owns 3072 edges (256 thr x 3 groups x 4 edges).
// ---------------------------------------------------------------------------
__global__ __launch_bounds__(256)
void scatter_kernel(const int* __restrict__ src,
                    const int* __restrict__ dst,
                    const int* __restrict__ et) {
    __shared__ int cnt[NUM_RELS];
    __shared__ int base[NUM_RELS];
    const int lo = blockIdx.x * 3072;

    for (int i = threadIdx.x; i < NUM_RELS; i += blockDim.x) cnt[i] = 0;
    __syncthreads();

    int4 rv[3], sv[3], dv[3];
    int  rk[3][4];
    bool ok[3];

#pragma unroll
    for (int g = 0; g < 3; g++) {
        int b = lo + g * 1024 + threadIdx.x * 4;
        ok[g] = (b + 3) < N_EDGES;          // group-aligned: all-or-nothing
        if (ok[g]) {
            rv[g] = *reinterpret_cast<const int4*>(et  + b);
            sv[g] = *reinterpret_cast<const int4*>(src + b);
            dv[g] = *reinterpret_cast<const int4*>(dst + b);
            rk[g][0] = atomicAdd(&cnt[rv[g].x], 1);
            rk[g][1] = atomicAdd(&cnt[rv[g].y], 1);
            rk[g][2] = atomicAdd(&cnt[rv[g].z], 1);
            rk[g][3] = atomicAdd(&cnt[rv[g].w], 1);
        }
    }
    __syncthreads();

    // One returned global atomic per (block, rel): ~520 per address chain.
    for (int i = threadIdx.x; i < NUM_RELS; i += blockDim.x) {
        int c = cnt[i];
        base[i] = c ? atomicAdd(&g_cursor[i], c) : 0;
    }
    __syncthreads();

#pragma unroll
    for (int g = 0; g < 3; g++) {
        if (ok[g]) {
            g_edges_s[rv[g].x * CAP + base[rv[g].x] + rk[g][0]] = make_int2(sv[g].x, dv[g].x);
            g_edges_s[rv[g].y * CAP + base[rv[g].y] + rk[g][1]] = make_int2(sv[g].y, dv[g].y);
            g_edges_s[rv[g].z * CAP + base[rv[g].z] + rk[g][2]] = make_int2(sv[g].z, dv[g].z);
            g_edges_s[rv[g].w * CAP + base[rv[g].w] + rk[g][3]] = make_int2(sv[g].w, dv[g].w);
        }
    }
}

// ---------------------------------------------------------------------------
// Edge kernel over bin slot-space. 512 thr x 2 CTAs/SM (105.6KB SMEM each);
// rel is warp-uniform within a bin. LSU diet: W via 28 LDS.128 broadcasts
// (padded-28 layout), gate_weight via 5 LDS.128, bias_term + gate_bias via
// warp-uniform __ldg (single-line, L1-hot 16KB tables).
// ---------------------------------------------------------------------------
__global__ __launch_bounds__(512, 2)
void edge_kernel(const float* __restrict__ h,
                 const float* __restrict__ weight,      // [200, 100]
                 const float* __restrict__ bias_term,   // [200, 20]
                 const float* __restrict__ gate_weight, // [200, 20]
                 const float* __restrict__ gate_bias,   // [200]
                 float* __restrict__ out) {
    extern __shared__ float sm[];
    float* Wsh  = sm + SM_W_OFF;
    float* gwsh = sm + SM_GW_OFF;

    for (int i = threadIdx.x; i < NUM_RELS * W_REL_STRIDE; i += blockDim.x) {
        int r  = i / W_REL_STRIDE;
        int k  = i % W_REL_STRIDE;
        int b  = k / W_BLK_STRIDE;
        int kk = k % W_BLK_STRIDE;
        Wsh[i] = (kk < 25) ? weight[r * 100 + b * 25 + kk] : 0.0f;
    }
    for (int i = threadIdx.x; i < NUM_RELS * 20; i += blockDim.x) gwsh[i] = gate_weight[i];
    __syncthreads();

    const int stride = gridDim.x * blockDim.x;
    for (int slot = blockIdx.x * blockDim.x + threadIdx.x; slot < TOTAL_SLOTS; slot += stride) {
        int r   = slot / CAP;
        int idx = slot - r * CAP;

        // Independent loads issued together; record read always safe.
        int2 ed  = __ldg(&g_edges_s[slot]);
        int cnt  = __ldg(&g_cursor[r]);
        float gb = __ldg(&gate_bias[r]);
        if (idx >= cnt) continue;

        int s = ed.x, d = ed.y;

        // gather source features (5 outstanding LDG.128) + uniform bias rows
        const float4* h4  = reinterpret_cast<const float4*>(h + (size_t)s * IN_FEAT);
        const float4* bt4 = reinterpret_cast<const float4*>(bias_term + r * 20);
        float4 t[5], bv[5];
#pragma unroll
        for (int i = 0; i < 5; i++) t[i] = __ldg(&h4[i]);
#pragma unroll
        for (int i = 0; i < 5; i++) bv[i] = __ldg(&bt4[i]);

        float x[IN_FEAT];
#pragma unroll
        for (int i = 0; i < 5; i++) {
            x[4*i+0] = t[i].x; x[4*i+1] = t[i].y; x[4*i+2] = t[i].z; x[4*i+3] = t[i].w;
        }

        // gate = sigmoid(dot(x, gw[r]) + gb)
        const float4* gw4 = reinterpret_cast<const float4*>(gwsh + r * 20);
        float g = gb;
#pragma unroll
        for (int k = 0; k < 5; k++) {
            float4 wv = gw4[k];
            g = fmaf(x[4*k+0], wv.x, g);
            g = fmaf(x[4*k+1], wv.y, g);
            g = fmaf(x[4*k+2], wv.z, g);
            g = fmaf(x[4*k+3], wv.w, g);
        }
        float gate = 1.0f / (1.0f + __expf(-g));

        // block-diagonal matmul: W via aligned LDS.128 broadcasts
        float m[OUT_FEAT];
        const float* Wr = Wsh + r * W_REL_STRIDE;
#pragma unroll
        for (int b = 0; b < 4; b++) {
            float wb[W_BLK_STRIDE];
            const float4* wp = reinterpret_cast<const float4*>(Wr + b * W_BLK_STRIDE);
#pragma unroll
            for (int k = 0; k < 7; k++)
                reinterpret_cast<float4*>(wb)[k] = wp[k];
#pragma unroll
            for (int o = 0; o < 5; o++) {
                float acc =        x[b*5+0] * wb[o];
                acc = fmaf(x[b*5+1], wb[5  + o], acc);
                acc = fmaf(x[b*5+2], wb[10 + o], acc);
                acc = fmaf(x[b*5+3], wb[15 + o], acc);
                acc = fmaf(x[b*5+4], wb[20 + o], acc);
                m[b*5 + o] = acc;
            }
        }

        // gated + biased vector scatter-add
        float* op = out + (size_t)d * OUT_FEAT;
#pragma unroll
        for (int k = 0; k < 5; k++) {
            red_add_v4(op + 4*k,
                       gate * (m[4*k+0] + bv[k].x),
                       gate * (m[4*k+1] + bv[k].y),
                       gate * (m[4*k+2] + bv[k].z),
                       gate * (m[4*k+3] + bv[k].w));
        }
    }
}

// ---------------------------------------------------------------------------
// Finalize: out[n,:] = relu(out[n,:] + h[n,:] @ loop_weight)
// ---------------------------------------------------------------------------
__global__ void finalize_kernel(const float* __restrict__ h,
                                const float* __restrict__ loop_w,
                                float* __restrict__ out) {
    __shared__ float w[IN_FEAT * OUT_FEAT];
    for (int i = threadIdx.x; i < IN_FEAT * OUT_FEAT; i += blockDim.x)
        w[i] = loop_w[i];
    __syncthreads();

    int n = blockIdx.x * blockDim.x + threadIdx.x;
    if (n >= N_NODES) return;

    const float4* h4 = reinterpret_cast<const float4*>(h + (size_t)n * IN_FEAT);
    float4* o4 = reinterpret_cast<float4*>(out + (size_t)n * OUT_FEAT);

    float4 acc[5];
    float x[IN_FEAT];
#pragma unroll
    for (int i = 0; i < 5; i++) {
        float4 t = h4[i];
        x[4*i+0] = t.x; x[4*i+1] = t.y; x[4*i+2] = t.z; x[4*i+3] = t.w;
        acc[i] = o4[i];   // aggregated messages
    }

#pragma unroll
    for (int i = 0; i < IN_FEAT; i++) {
        float xi = x[i];
        const float4* wr = reinterpret_cast<const float4*>(w + i * OUT_FEAT);
#pragma unroll
        for (int k = 0; k < 5; k++) {
            float4 wv = wr[k];
            acc[k].x = fmaf(xi, wv.x, acc[k].x);
            acc[k].y = fmaf(xi, wv.y, acc[k].y);
            acc[k].z = fmaf(xi, wv.z, acc[k].z);
            acc[k].w = fmaf(xi, wv.w, acc[k].w);
        }
    }

#pragma unroll
    for (int k = 0; k < 5; k++) {
        acc[k].x = fmaxf(acc[k].x, 0.0f);
        acc[k].y = fmaxf(acc[k].y, 0.0f);
        acc[k].z = fmaxf(acc[k].z, 0.0f);
        acc[k].w = fmaxf(acc[k].w, 0.0f);
        o4[k] = acc[k];
    }
}

// ---------------------------------------------------------------------------
// Launch
// ---------------------------------------------------------------------------
extern "C" void kernel_launch(void* const* d_in, const int* in_sizes, int n_in,
                              void* d_out, int out_size) {
    const float* h           = (const float*)d_in[0];
    const float* weight      = (const float*)d_in[1];
    const float* bias_term   = (const float*)d_in[2];
    const float* gate_weight = (const float*)d_in[3];
    const float* gate_bias   = (const float*)d_in[4];
    const float* loop_weight = (const float*)d_in[5];
    const int*   edge_src    = (const int*)d_in[6];
    const int*   edge_dst    = (const int*)d_in[7];
    const int*   etype       = (const int*)d_in[8];
    float* out = (float*)d_out;

    // Zero accumulator + bin cursors (memset nodes, graph-capturable)
    void* cur_addr = nullptr;
    cudaGetSymbolAddress(&cur_addr, g_cursor);
    cudaMemsetAsync(out, 0, (size_t)N_NODES * OUT_FEAT * sizeof(float), 0);
    cudaMemsetAsync(cur_addr, 0, NUM_RELS * sizeof(int), 0);

    // Single-pass binning by relation (rank from pass-1 atomic return)
    scatter_kernel<<<(N_EDGES + 3071) / 3072, 256>>>(edge_src, edge_dst, etype);

    // Edge kernel, 512 thr x 2 CTAs/SM
    cudaFuncSetAttribute(edge_kernel, cudaFuncAttributeMaxDynamicSharedMemorySize, SM_BYTES);
    edge_kernel<<<296, 512, SM_BYTES>>>(h, weight, bias_term, gate_weight, gate_bias, out);

    // Fused self-loop GEMM + ReLU
    finalize_kernel<<<(N_NODES + 255) / 256, 256>>>(h, loop_weight, out);
}

// round 10
// speedup vs baseline: 1.0937x; 1.0937x over previous
#include <cuda_runtime.h>
#include <cuda_bf16.h>

#define N_NODES   100000
#define N_EDGES   1600000
#define NUM_RELS  200
#define IN_FEAT   20
#define OUT_FEAT  20

// Fixed-capacity relation bins: mean 8000 edges/rel, sd ~89. CAP = +7.9 sigma.
#define CAP        8704
#define TOTAL_SLOTS (NUM_RELS * CAP)

// SMEM layout for edge kernel (floats): W stride 25 (unpadded), gw, bias.
#define SM_W_OFF   0
#define SM_GW_OFF  (NUM_RELS * 100)              // 20000
#define SM_B_OFF   (SM_GW_OFF + NUM_RELS * 20)   // 24000
#define SM_FLOATS  (SM_B_OFF + NUM_RELS * 20)    // 28000
#define SM_BYTES   (SM_FLOATS * 4)               // 112000 -> 2 CTAs/SM

// ---------------------------------------------------------------------------
// Static scratch (no cudaMalloc allowed)
// ---------------------------------------------------------------------------
__device__ int  g_cursor[NUM_RELS];
__device__ int2 g_edges_s[TOTAL_SLOTS];   // (src, dst) in rel-strided bins

__device__ __forceinline__ void red_add_v4(float* addr, float a, float b, float c, float d) {
    asm volatile("red.global.add.v4.f32 [%0], {%1, %2, %3, %4};"
                 :: "l"(addr), "f"(a), "f"(b), "f"(c), "f"(d)
                 : "memory");
}

// ---------------------------------------------------------------------------
// Scatter: ONE SMEM-atomic pass (pass-1 atomicAdd return IS the local rank).
// 2 groups x 4 edges per thread (2048/block) — lower regs, higher occupancy.
// ---------------------------------------------------------------------------
__global__ __launch_bounds__(256)
void scatter_kernel(const int* __restrict__ src,
                    const int* __restrict__ dst,
                    const int* __restrict__ et) {
    __shared__ int cnt[NUM_RELS];
    __shared__ int base[NUM_RELS];
    const int lo = blockIdx.x * 2048;

    for (int i = threadIdx.x; i < NUM_RELS; i += blockDim.x) cnt[i] = 0;
    __syncthreads();

    int4 rv[2], sv[2], dv[2];
    int  rk[2][4];
    bool ok[2];

#pragma unroll
    for (int g = 0; g < 2; g++) {
        int b = lo + g * 1024 + threadIdx.x * 4;
        ok[g] = (b + 3) < N_EDGES;          // 4-aligned: all-or-nothing
        if (ok[g]) {
            rv[g] = *reinterpret_cast<const int4*>(et  + b);
            sv[g] = *reinterpret_cast<const int4*>(src + b);
            dv[g] = *reinterpret_cast<const int4*>(dst + b);
            rk[g][0] = atomicAdd(&cnt[rv[g].x], 1);
            rk[g][1] = atomicAdd(&cnt[rv[g].y], 1);
            rk[g][2] = atomicAdd(&cnt[rv[g].z], 1);
            rk[g][3] = atomicAdd(&cnt[rv[g].w], 1);
        }
    }
    __syncthreads();

    // One returned global atomic per (block, rel)
    for (int i = threadIdx.x; i < NUM_RELS; i += blockDim.x) {
        int c = cnt[i];
        base[i] = c ? atomicAdd(&g_cursor[i], c) : 0;
    }
    __syncthreads();

#pragma unroll
    for (int g = 0; g < 2; g++) {
        if (ok[g]) {
            g_edges_s[rv[g].x * CAP + base[rv[g].x] + rk[g][0]] = make_int2(sv[g].x, dv[g].x);
            g_edges_s[rv[g].y * CAP + base[rv[g].y] + rk[g][1]] = make_int2(sv[g].y, dv[g].y);
            g_edges_s[rv[g].z * CAP + base[rv[g].z] + rk[g][2]] = make_int2(sv[g].z, dv[g].z);
            g_edges_s[rv[g].w * CAP + base[rv[g].w] + rk[g][3]] = make_int2(sv[g].w, dv[g].w);
        }
    }
}

// ---------------------------------------------------------------------------
// Edge kernel: EXACT round-6 form (measured best). 512 thr x 2 CTAs/SM,
// all tables in SMEM, W via scalar broadcast LDS consumed directly by FMAs
// (no staging arrays -> no spills at the 64-reg cap).
// ---------------------------------------------------------------------------
__global__ __launch_bounds__(512, 2)
void edge_kernel(const float* __restrict__ h,
                 const float* __restrict__ weight,      // [200, 100]
                 const float* __restrict__ bias_term,   // [200, 20]
                 const float* __restrict__ gate_weight, // [200, 20]
                 const float* __restrict__ gate_bias,   // [200]
                 float* __restrict__ out) {
    extern __shared__ float sm[];
    float* Wsh  = sm + SM_W_OFF;
    float* gwsh = sm + SM_GW_OFF;
    float* bsh  = sm + SM_B_OFF;

    for (int i = threadIdx.x; i < NUM_RELS * 100; i += blockDim.x) Wsh[i]  = weight[i];
    for (int i = threadIdx.x; i < NUM_RELS * 20;  i += blockDim.x) gwsh[i] = gate_weight[i];
    for (int i = threadIdx.x; i < NUM_RELS * 20;  i += blockDim.x) bsh[i]  = bias_term[i];
    __syncthreads();

    const int stride = gridDim.x * blockDim.x;
    for (int slot = blockIdx.x * blockDim.x + threadIdx.x; slot < TOTAL_SLOTS; slot += stride) {
        int r   = slot / CAP;
        int idx = slot - r * CAP;

        // Independent loads issued together; record read always safe.
        int2 ed  = __ldg(&g_edges_s[slot]);
        int cnt  = __ldg(&g_cursor[r]);
        float gb = __ldg(&gate_bias[r]);
        if (idx >= cnt) continue;

        int s = ed.x, d = ed.y;

        // gather source features (5 outstanding LDG.128)
        const float4* h4 = reinterpret_cast<const float4*>(h + (size_t)s * IN_FEAT);
        float4 t[5];
#pragma unroll
        for (int i = 0; i < 5; i++) t[i] = __ldg(&h4[i]);
        float x[IN_FEAT];
#pragma unroll
        for (int i = 0; i < 5; i++) {
            x[4*i+0] = t[i].x; x[4*i+1] = t[i].y; x[4*i+2] = t[i].z; x[4*i+3] = t[i].w;
        }

        // gate = sigmoid(dot(x, gw[r]) + gb)
        const float4* gw4 = reinterpret_cast<const float4*>(gwsh + r * 20);
        float g = gb;
#pragma unroll
        for (int k = 0; k < 5; k++) {
            float4 wv = gw4[k];
            g = fmaf(x[4*k+0], wv.x, g);
            g = fmaf(x[4*k+1], wv.y, g);
            g = fmaf(x[4*k+2], wv.z, g);
            g = fmaf(x[4*k+3], wv.w, g);
        }
        float gate = 1.0f / (1.0f + __expf(-g));

        // block-diagonal matmul: scalar broadcast LDS consumed directly
        float m[OUT_FEAT];
        const float* Wr = Wsh + r * 100;
#pragma unroll
        for (int b = 0; b < 4; b++) {
            const float* wb = Wr + b * 25;
            float x0 = x[b*5+0], x1 = x[b*5+1], x2 = x[b*5+2], x3 = x[b*5+3], x4 = x[b*5+4];
#pragma unroll
            for (int o = 0; o < 5; o++) {
                float acc =        x0 * wb[o];
                acc = fmaf(x1, wb[5  + o], acc);
                acc = fmaf(x2, wb[10 + o], acc);
                acc = fmaf(x3, wb[15 + o], acc);
                acc = fmaf(x4, wb[20 + o], acc);
                m[b*5 + o] = acc;
            }
        }

        // gated + biased vector scatter-add
        const float4* br4 = reinterpret_cast<const float4*>(bsh + r * 20);
        float* op = out + (size_t)d * OUT_FEAT;
#pragma unroll
        for (int k = 0; k < 5; k++) {
            float4 bv = br4[k];
            red_add_v4(op + 4*k,
                       gate * (m[4*k+0] + bv.x),
                       gate * (m[4*k+1] + bv.y),
                       gate * (m[4*k+2] + bv.z),
                       gate * (m[4*k+3] + bv.w));
        }
    }
}

// ---------------------------------------------------------------------------
// Finalize: out[n,:] = relu(out[n,:] + h[n,:] @ loop_weight)
// ---------------------------------------------------------------------------
__global__ void finalize_kernel(const float* __restrict__ h,
                                const float* __restrict__ loop_w,
                                float* __restrict__ out) {
    __shared__ float w[IN_FEAT * OUT_FEAT];
    for (int i = threadIdx.x; i < IN_FEAT * OUT_FEAT; i += blockDim.x)
        w[i] = loop_w[i];
    __syncthreads();

    int n = blockIdx.x * blockDim.x + threadIdx.x;
    if (n >= N_NODES) return;

    const float4* h4 = reinterpret_cast<const float4*>(h + (size_t)n * IN_FEAT);
    float4* o4 = reinterpret_cast<float4*>(out + (size_t)n * OUT_FEAT);

    float4 acc[5];
    float x[IN_FEAT];
#pragma unroll
    for (int i = 0; i < 5; i++) {
        float4 t = h4[i];
        x[4*i+0] = t.x; x[4*i+1] = t.y; x[4*i+2] = t.z; x[4*i+3] = t.w;
        acc[i] = o4[i];   // aggregated messages
    }

#pragma unroll
    for (int i = 0; i < IN_FEAT; i++) {
        float xi = x[i];
        const float4* wr = reinterpret_cast<const float4*>(w + i * OUT_FEAT);
#pragma unroll
        for (int k = 0; k < 5; k++) {
            float4 wv = wr[k];
            acc[k].x = fmaf(xi, wv.x, acc[k].x);
            acc[k].y = fmaf(xi, wv.y, acc[k].y);
            acc[k].z = fmaf(xi, wv.z, acc[k].z);
            acc[k].w = fmaf(xi, wv.w, acc[k].w);
        }
    }

#pragma unroll
    for (int k = 0; k < 5; k++) {
        acc[k].x = fmaxf(acc[k].x, 0.0f);
        acc[k].y = fmaxf(acc[k].y, 0.0f);
        acc[k].z = fmaxf(acc[k].z, 0.0f);
        acc[k].w = fmaxf(acc[k].w, 0.0f);
        o4[k] = acc[k];
    }
}

// ---------------------------------------------------------------------------
// Launch
// ---------------------------------------------------------------------------
extern "C" void kernel_launch(void* const* d_in, const int* in_sizes, int n_in,
                              void* d_out, int out_size) {
    const float* h           = (const float*)d_in[0];
    const float* weight      = (const float*)d_in[1];
    const float* bias_term   = (const float*)d_in[2];
    const float* gate_weight = (const float*)d_in[3];
    const float* gate_bias   = (const float*)d_in[4];
    const float* loop_weight = (const float*)d_in[5];
    const int*   edge_src    = (const int*)d_in[6];
    const int*   edge_dst    = (const int*)d_in[7];
    const int*   etype       = (const int*)d_in[8];
    float* out = (float*)d_out;

    // Zero accumulator + bin cursors
    void* cur_addr = nullptr;
    cudaGetSymbolAddress(&cur_addr, g_cursor);
    cudaMemsetAsync(out, 0, (size_t)N_NODES * OUT_FEAT * sizeof(float), 0);
    cudaMemsetAsync(cur_addr, 0, NUM_RELS * sizeof(int), 0);

    // Single-pass binning by relation
    scatter_kernel<<<(N_EDGES + 2047) / 2048, 256>>>(edge_src, edge_dst, etype);

    // Edge kernel, 512 thr x 2 CTAs/SM (round-6 exact)
    cudaFuncSetAttribute(edge_kernel, cudaFuncAttributeMaxDynamicSharedMemorySize, SM_BYTES);
    edge_kernel<<<296, 512, SM_BYTES>>>(h, weight, bias_term, gate_weight, gate_bias, out);

    // Fused self-loop GEMM + ReLU
    finalize_kernel<<<(N_NODES + 255) / 256, 256>>>(h, loop_weight, out);
}

// round 12
// speedup vs baseline: 1.1670x; 1.0670x over previous
#include <cuda_runtime.h>
#include <cuda_bf16.h>

#define N_NODES   100000
#define N_EDGES   1600000
#define NUM_RELS  200
#define IN_FEAT   20
#define OUT_FEAT  20

// Fixed-capacity relation bins: mean 8000 edges/rel, sd ~89. CAP = +7.9 sigma.
#define CAP        8704
#define TOTAL_SLOTS (NUM_RELS * CAP)

// SMEM layout for edge kernel (floats): W stride 25 (unpadded), gw, bias.
#define SM_W_OFF   0
#define SM_GW_OFF  (NUM_RELS * 100)              // 20000
#define SM_B_OFF   (SM_GW_OFF + NUM_RELS * 20)   // 24000
#define SM_FLOATS  (SM_B_OFF + NUM_RELS * 20)    // 28000
#define SM_BYTES   (SM_FLOATS * 4)               // 112000 -> 2 CTAs/SM

// Heterogeneous prologue grid: scatter blocks + loop_msg blocks
#define SCAT_BLOCKS 782                      // 782 * 2048 >= 1.6M edges
#define LOOP_BLOCKS ((N_NODES + 255) / 256)  // 391
#define PRO_BLOCKS  (SCAT_BLOCKS + LOOP_BLOCKS)

// ---------------------------------------------------------------------------
// Static scratch (no cudaMalloc allowed)
// ---------------------------------------------------------------------------
__device__ int  g_cursor[NUM_RELS];
__device__ int2 g_edges_s[TOTAL_SLOTS];   // (src, dst) in rel-strided bins

__device__ __forceinline__ void red_add_v4(float* addr, float a, float b, float c, float d) {
    asm volatile("red.global.add.v4.f32 [%0], {%1, %2, %3, %4};"
                 :: "l"(addr), "f"(a), "f"(b), "f"(c), "f"(d)
                 : "memory");
}

// ---------------------------------------------------------------------------
// Fused prologue: blocks [0, SCAT_BLOCKS) bin edges by relation (1-pass,
// rank from SMEM atomicAdd return); blocks [SCAT_BLOCKS, PRO_BLOCKS) compute
// out[n,:] = h[n,:] @ loop_weight. Independent work, disjoint resources
// (ATOMS/latency vs FMA/HBM) -> co-scheduled overlap.
// Shared 400-int array aliases: scatter = cnt[200]+base[200];
// loop path = 400-float weight tile (same 1600 bytes).
// ---------------------------------------------------------------------------
__global__ __launch_bounds__(256)
void prologue_kernel(const float* __restrict__ h,
                     const float* __restrict__ loop_w,
                     const int* __restrict__ src,
                     const int* __restrict__ dst,
                     const int* __restrict__ et,
                     float* __restrict__ out) {
    __shared__ int ism[2 * NUM_RELS];   // 400 ints == 400 floats

    if (blockIdx.x < SCAT_BLOCKS) {
        // ---------------- scatter path ----------------
        int* cnt  = ism;
        int* base = ism + NUM_RELS;
        const int lo = blockIdx.x * 2048;

        for (int i = threadIdx.x; i < NUM_RELS; i += blockDim.x) cnt[i] = 0;
        __syncthreads();

        int4 rv[2], sv[2], dv[2];
        int  rk[2][4];
        bool ok[2];

#pragma unroll
        for (int g = 0; g < 2; g++) {
            int b = lo + g * 1024 + threadIdx.x * 4;
            ok[g] = (b + 3) < N_EDGES;          // 4-aligned: all-or-nothing
            if (ok[g]) {
                rv[g] = *reinterpret_cast<const int4*>(et  + b);
                sv[g] = *reinterpret_cast<const int4*>(src + b);
                dv[g] = *reinterpret_cast<const int4*>(dst + b);
                rk[g][0] = atomicAdd(&cnt[rv[g].x], 1);
                rk[g][1] = atomicAdd(&cnt[rv[g].y], 1);
                rk[g][2] = atomicAdd(&cnt[rv[g].z], 1);
                rk[g][3] = atomicAdd(&cnt[rv[g].w], 1);
            }
        }
        __syncthreads();

        // One returned global atomic per (block, rel)
        for (int i = threadIdx.x; i < NUM_RELS; i += blockDim.x) {
            int c = cnt[i];
            base[i] = c ? atomicAdd(&g_cursor[i], c) : 0;
        }
        __syncthreads();

#pragma unroll
        for (int g = 0; g < 2; g++) {
            if (ok[g]) {
                g_edges_s[rv[g].x * CAP + base[rv[g].x] + rk[g][0]] = make_int2(sv[g].x, dv[g].x);
                g_edges_s[rv[g].y * CAP + base[rv[g].y] + rk[g][1]] = make_int2(sv[g].y, dv[g].y);
                g_edges_s[rv[g].z * CAP + base[rv[g].z] + rk[g][2]] = make_int2(sv[g].z, dv[g].z);
                g_edges_s[rv[g].w * CAP + base[rv[g].w] + rk[g][3]] = make_int2(sv[g].w, dv[g].w);
            }
        }
    } else {
        // ---------------- loop-message path ----------------
        float* w = reinterpret_cast<float*>(ism);  // 400 floats, exactly fits
        for (int i = threadIdx.x; i < IN_FEAT * OUT_FEAT; i += blockDim.x)
            w[i] = loop_w[i];
        __syncthreads();

        int n = (blockIdx.x - SCAT_BLOCKS) * blockDim.x + threadIdx.x;
        if (n >= N_NODES) return;

        const float4* h4 = reinterpret_cast<const float4*>(h + (size_t)n * IN_FEAT);
        float x[IN_FEAT];
#pragma unroll
        for (int i = 0; i < 5; i++) {
            float4 t = h4[i];
            x[4*i+0] = t.x; x[4*i+1] = t.y; x[4*i+2] = t.z; x[4*i+3] = t.w;
        }

        float4 acc[5];
#pragma unroll
        for (int k = 0; k < 5; k++) acc[k] = make_float4(0.f, 0.f, 0.f, 0.f);

#pragma unroll
        for (int i = 0; i < IN_FEAT; i++) {
            float xi = x[i];
            const float4* wr = reinterpret_cast<const float4*>(w + i * OUT_FEAT);
#pragma unroll
            for (int k = 0; k < 5; k++) {
                float4 wv = wr[k];
                acc[k].x = fmaf(xi, wv.x, acc[k].x);
                acc[k].y = fmaf(xi, wv.y, acc[k].y);
                acc[k].z = fmaf(xi, wv.z, acc[k].z);
                acc[k].w = fmaf(xi, wv.w, acc[k].w);
            }
        }

        float4* o4 = reinterpret_cast<float4*>(out + (size_t)n * OUT_FEAT);
#pragma unroll
        for (int k = 0; k < 5; k++) o4[k] = acc[k];
    }
}

// ---------------------------------------------------------------------------
// Edge kernel: EXACT round-6 form (measured best). 512 thr x 2 CTAs/SM,
// all tables in SMEM, W via scalar broadcast LDS consumed directly by FMAs.
// ---------------------------------------------------------------------------
__global__ __launch_bounds__(512, 2)
void edge_kernel(const float* __restrict__ h,
                 const float* __restrict__ weight,      // [200, 100]
                 const float* __restrict__ bias_term,   // [200, 20]
                 const float* __restrict__ gate_weight, // [200, 20]
                 const float* __restrict__ gate_bias,   // [200]
                 float* __restrict__ out) {
    extern __shared__ float sm[];
    float* Wsh  = sm + SM_W_OFF;
    float* gwsh = sm + SM_GW_OFF;
    float* bsh  = sm + SM_B_OFF;

    for (int i = threadIdx.x; i < NUM_RELS * 100; i += blockDim.x) Wsh[i]  = weight[i];
    for (int i = threadIdx.x; i < NUM_RELS * 20;  i += blockDim.x) gwsh[i] = gate_weight[i];
    for (int i = threadIdx.x; i < NUM_RELS * 20;  i += blockDim.x) bsh[i]  = bias_term[i];
    __syncthreads();

    const int stride = gridDim.x * blockDim.x;
    for (int slot = blockIdx.x * blockDim.x + threadIdx.x; slot < TOTAL_SLOTS; slot += stride) {
        int r   = slot / CAP;
        int idx = slot - r * CAP;

        int2 ed  = __ldg(&g_edges_s[slot]);
        int cnt  = __ldg(&g_cursor[r]);
        float gb = __ldg(&gate_bias[r]);
        if (idx >= cnt) continue;

        int s = ed.x, d = ed.y;

        const float4* h4 = reinterpret_cast<const float4*>(h + (size_t)s * IN_FEAT);
        float4 t[5];
#pragma unroll
        for (int i = 0; i < 5; i++) t[i] = __ldg(&h4[i]);
        float x[IN_FEAT];
#pragma unroll
        for (int i = 0; i < 5; i++) {
            x[4*i+0] = t[i].x; x[4*i+1] = t[i].y; x[4*i+2] = t[i].z; x[4*i+3] = t[i].w;
        }

        const float4* gw4 = reinterpret_cast<const float4*>(gwsh + r * 20);
        float g = gb;
#pragma unroll
        for (int k = 0; k < 5; k++) {
            float4 wv = gw4[k];
            g = fmaf(x[4*k+0], wv.x, g);
            g = fmaf(x[4*k+1], wv.y, g);
            g = fmaf(x[4*k+2], wv.z, g);
            g = fmaf(x[4*k+3], wv.w, g);
        }
        float gate = 1.0f / (1.0f + __expf(-g));

        float m[OUT_FEAT];
        const float* Wr = Wsh + r * 100;
#pragma unroll
        for (int b = 0; b < 4; b++) {
            const float* wb = Wr + b * 25;
            float x0 = x[b*5+0], x1 = x[b*5+1], x2 = x[b*5+2], x3 = x[b*5+3], x4 = x[b*5+4];
#pragma unroll
            for (int o = 0; o < 5; o++) {
                float acc =        x0 * wb[o];
                acc = fmaf(x1, wb[5  + o], acc);
                acc = fmaf(x2, wb[10 + o], acc);
                acc = fmaf(x3, wb[15 + o], acc);
                acc = fmaf(x4, wb[20 + o], acc);
                m[b*5 + o] = acc;
            }
        }

        const float4* br4 = reinterpret_cast<const float4*>(bsh + r * 20);
        float* op = out + (size_t)d * OUT_FEAT;
#pragma unroll
        for (int k = 0; k < 5; k++) {
            float4 bv = br4[k];
            red_add_v4(op + 4*k,
                       gate * (m[4*k+0] + bv.x),
                       gate * (m[4*k+1] + bv.y),
                       gate * (m[4*k+2] + bv.z),
                       gate * (m[4*k+3] + bv.w));
        }
    }
}

// ---------------------------------------------------------------------------
// Kernel C: in-place ReLU (round-6 exact)
// ---------------------------------------------------------------------------
__global__ void relu_kernel(float* __restrict__ out, int n4) {
    int i = blockIdx.x * blockDim.x + threadIdx.x;
    if (i >= n4) return;
    float4* p = reinterpret_cast<float4*>(out);
    float4 v = p[i];
    v.x = fmaxf(v.x, 0.0f);
    v.y = fmaxf(v.y, 0.0f);
    v.z = fmaxf(v.z, 0.0f);
    v.w = fmaxf(v.w, 0.0f);
    p[i] = v;
}

// ---------------------------------------------------------------------------
// Launch
// ---------------------------------------------------------------------------
extern "C" void kernel_launch(void* const* d_in, const int* in_sizes, int n_in,
                              void* d_out, int out_size) {
    const float* h           = (const float*)d_in[0];
    const float* weight      = (const float*)d_in[1];
    const float* bias_term   = (const float*)d_in[2];
    const float* gate_weight = (const float*)d_in[3];
    const float* gate_bias   = (const float*)d_in[4];
    const float* loop_weight = (const float*)d_in[5];
    const int*   edge_src    = (const int*)d_in[6];
    const int*   edge_dst    = (const int*)d_in[7];
    const int*   etype       = (const int*)d_in[8];
    float* out = (float*)d_out;

    // Zero bin cursors (800 bytes)
    void* cur_addr = nullptr;
    cudaGetSymbolAddress(&cur_addr, g_cursor);
    cudaMemsetAsync(cur_addr, 0, NUM_RELS * sizeof(int), 0);

    // Fused prologue: scatter blocks + loop-message blocks, co-scheduled
    prologue_kernel<<<PRO_BLOCKS, 256>>>(h, loop_weight,
                                         edge_src, edge_dst, etype, out);

    // Edge kernel, 512 thr x 2 CTAs/SM (round-6 exact)
    cudaFuncSetAttribute(edge_kernel, cudaFuncAttributeMaxDynamicSharedMemorySize, SM_BYTES);
    edge_kernel<<<296, 512, SM_BYTES>>>(h, weight, bias_term, gate_weight, gate_bias, out);

    // ReLU in place
    int n4 = (N_NODES * OUT_FEAT) / 4;
    relu_kernel<<<(n4 + 255) / 256, 256>>>(out, n4);
}